// round 1
// baseline (speedup 1.0000x reference)
#include <cuda_runtime.h>

#define NN 100000
#define NE 1600000
#define NS 3
#define DIN 128
#define DOUT 64
#define ROW (NS*DOUT)   /* 192 floats per node state row */
#define DEPTH 10

// ---------------- device scratch (static: no allocation allowed) ----------------
__device__ float g_emb [NN*ROW];
__device__ float g_bufA[NN*ROW];
__device__ float g_bufB[NN*ROW];
__device__ int   g_cnt[NN];
__device__ int   g_rowptr[NN+1];
__device__ int   g_cursor[NN];
__device__ float g_deginv[NN];
__device__ int   g_col[NE];
__device__ int   g_scan[NN];
__device__ int   g_bsum[128];
__device__ int   g_boff[128];

// ---------------- CSR build (counting sort by tgt) ----------------
__global__ void k_zero() {
    int i = blockIdx.x*blockDim.x + threadIdx.x;
    if (i < NN) g_cnt[i] = 0;
}

__global__ void k_hist(const int* __restrict__ tgt) {
    int e = blockIdx.x*blockDim.x + threadIdx.x;
    if (e < NE) atomicAdd(&g_cnt[tgt[e]], 1);
}

__global__ void k_scan1() {
    __shared__ int sh[1024];
    int t = threadIdx.x;
    int i = blockIdx.x*1024 + t;
    int v = (i < NN) ? g_cnt[i] : 0;
    sh[t] = v;
    __syncthreads();
    for (int off = 1; off < 1024; off <<= 1) {
        int add = (t >= off) ? sh[t-off] : 0;
        __syncthreads();
        sh[t] += add;
        __syncthreads();
    }
    if (i < NN) g_scan[i] = sh[t];
    if (t == 1023) g_bsum[blockIdx.x] = sh[1023];
}

__global__ void k_scan2(int nb) {
    if (threadIdx.x == 0 && blockIdx.x == 0) {
        int run = 0;
        for (int b = 0; b < nb; b++) { g_boff[b] = run; run += g_bsum[b]; }
    }
}

__global__ void k_scan3() {
    int i = blockIdx.x*blockDim.x + threadIdx.x;
    if (i < NN) {
        int cnt  = g_cnt[i];
        int excl = g_scan[i] - cnt + g_boff[i >> 10];
        g_rowptr[i] = excl;
        g_cursor[i] = excl;
        g_deginv[i] = 1.0f / (float)max(cnt, 1);
        if (i == 0) g_rowptr[NN] = NE;
    }
}

__global__ void k_fill(const int* __restrict__ src, const int* __restrict__ tgt) {
    int e = blockIdx.x*blockDim.x + threadIdx.x;
    if (e < NE) {
        int p = atomicAdd(&g_cursor[tgt[e]], 1);
        g_col[p] = src[e];
    }
}

// ---------------- emb = data @ Ws + bs, laid out [N][S*64] ----------------
__global__ void k_emb(const float* __restrict__ data, const float* __restrict__ Ws,
                      const float* __restrict__ bs) {
    __shared__ float sd[4*DIN];
    int s  = blockIdx.y;
    int n0 = blockIdx.x * 4;
    int tid = threadIdx.x;
    for (int i = tid; i < 4*DIN; i += 256) sd[i] = data[n0*DIN + i];
    __syncthreads();
    int ln = tid >> 6;      // 0..3  (node within block)
    int o  = tid & 63;      // output dim
    const float* W  = Ws + s*DIN*DOUT;
    const float* dr = sd + ln*DIN;
    float acc = bs[s*DOUT + o];
    #pragma unroll 8
    for (int k = 0; k < DIN; k++) acc += dr[k] * W[k*DOUT + o];
    g_emb[(n0+ln)*ROW + s*DOUT + o] = acc;
}

// ---------------- one propagation step, all 3 scales fused ----------------
// out = (1-t)*(x - mean_in(x)) + t*emb   (deg>0), else  t*emb
__global__ void k_prop(const float* __restrict__ x, float* __restrict__ y) {
    int w    = (blockIdx.x*blockDim.x + threadIdx.x) >> 5;
    int lane = threadIdx.x & 31;
    if (w >= NN) return;
    int beg = g_rowptr[w], end = g_rowptr[w+1];

    float a0x=0.f,a0y=0.f,a1x=0.f,a1y=0.f,a2x=0.f,a2y=0.f;
    for (int j = beg; j < end; j++) {
        int c = __ldg(&g_col[j]);
        const float2* xr = (const float2*)(x + (size_t)c*ROW);
        float2 v0 = xr[lane];
        float2 v1 = xr[32 + lane];
        float2 v2 = xr[64 + lane];
        a0x += v0.x; a0y += v0.y;
        a1x += v1.x; a1y += v1.y;
        a2x += v2.x; a2y += v2.y;
    }

    const float2* em = (const float2*)(g_emb + (size_t)w*ROW);
    float2* yr = (float2*)(y + (size_t)w*ROW);
    float2 e0 = em[lane], e1 = em[32+lane], e2 = em[64+lane];
    const float t0 = 0.1f, t1 = 0.2f, t2 = 0.3f;

    if (end > beg) {
        float dinv = g_deginv[w];
        const float2* xo = (const float2*)(x + (size_t)w*ROW);
        float2 o0 = xo[lane], o1 = xo[32+lane], o2 = xo[64+lane];
        float2 r;
        r.x = (1.f-t0)*(o0.x - a0x*dinv) + t0*e0.x;
        r.y = (1.f-t0)*(o0.y - a0y*dinv) + t0*e0.y;  yr[lane]      = r;
        r.x = (1.f-t1)*(o1.x - a1x*dinv) + t1*e1.x;
        r.y = (1.f-t1)*(o1.y - a1y*dinv) + t1*e1.y;  yr[32 + lane] = r;
        r.x = (1.f-t2)*(o2.x - a2x*dinv) + t2*e2.x;
        r.y = (1.f-t2)*(o2.y - a2y*dinv) + t2*e2.y;  yr[64 + lane] = r;
    } else {
        yr[lane]      = make_float2(t0*e0.x, t0*e0.y);
        yr[32 + lane] = make_float2(t1*e1.x, t1*e1.y);
        yr[64 + lane] = make_float2(t2*e2.x, t2*e2.y);
    }
}

// ---------------- fused attention epilogue, warp per node ----------------
__global__ void k_final(const float* __restrict__ xin, const float* __restrict__ data,
                        const float* __restrict__ W_src, const float* __restrict__ b_src,
                        const float* __restrict__ W_tgt, const float* __restrict__ b_tgt,
                        float* __restrict__ out) {
    __shared__ float sd[8][DIN];
    __shared__ float ss[8][DOUT];
    int wid  = threadIdx.x >> 5;
    int lane = threadIdx.x & 31;
    int n = blockIdx.x*8 + wid;
    if (n >= NN) return;

    // stage the data row in shared
    float4 dv = ((const float4*)(data + (size_t)n*DIN))[lane];
    ((float4*)sd[wid])[lane] = dv;
    __syncwarp();

    // s_att[o] = b_src[o] + data[n] . W_src[:,o]  for o = lane, lane+32
    float a0 = b_src[lane], a1 = b_src[lane + 32];
    #pragma unroll 8
    for (int k = 0; k < DIN; k++) {
        float d = sd[wid][k];
        a0 += d * W_src[k*DOUT + lane];
        a1 += d * W_src[k*DOUT + lane + 32];
    }
    ss[wid][lane] = a0; ss[wid][lane + 32] = a1;
    __syncwarp();

    // scales = relu(out10)
    const float* xr = xin + (size_t)n*ROW;
    float sc[NS][2];
    #pragma unroll
    for (int s = 0; s < NS; s++) {
        sc[s][0] = fmaxf(xr[s*DOUT + lane],      0.f);
        sc[s][1] = fmaxf(xr[s*DOUT + lane + 32], 0.f);
    }

    // u[p] = W_tgt[p,:] . s_att   for p = lane, lane+32
    float u0 = 0.f, u1 = 0.f;
    #pragma unroll 8
    for (int o = 0; o < DOUT; o++) {
        float sa = ss[wid][o];
        u0 += W_tgt[lane*DOUT + o]        * sa;
        u1 += W_tgt[(lane + 32)*DOUT + o] * sa;
    }

    // c = b_tgt . s_att (warp-reduced)
    float cp = b_tgt[lane]*ss[wid][lane] + b_tgt[lane+32]*ss[wid][lane+32];
    for (int m = 16; m; m >>= 1) cp += __shfl_xor_sync(0xffffffffu, cp, m);

    // logits[s] = scales[s,:] . u + c
    float lg[NS];
    #pragma unroll
    for (int s = 0; s < NS; s++) {
        float p = sc[s][0]*u0 + sc[s][1]*u1;
        for (int m = 16; m; m >>= 1) p += __shfl_xor_sync(0xffffffffu, p, m);
        lg[s] = p + cp;
    }

    float mx = fmaxf(lg[0], fmaxf(lg[1], lg[2]));
    float e0 = expf(lg[0]-mx), e1 = expf(lg[1]-mx), e2 = expf(lg[2]-mx);
    float inv = 1.f / (e0 + e1 + e2);
    float w0 = e0*inv, w1 = e1*inv, w2 = e2*inv;

    out[(size_t)n*DOUT + lane]      = w0*sc[0][0] + w1*sc[1][0] + w2*sc[2][0];
    out[(size_t)n*DOUT + lane + 32] = w0*sc[0][1] + w1*sc[1][1] + w2*sc[2][1];
}

// ---------------- launch ----------------
extern "C" void kernel_launch(void* const* d_in, const int* in_sizes, int n_in,
                              void* d_out, int out_size) {
    const float* data  = (const float*)d_in[0];
    const int*   src   = (const int*)  d_in[1];
    const int*   tgt   = (const int*)  d_in[2];
    const float* Ws    = (const float*)d_in[3];
    const float* bs    = (const float*)d_in[4];
    const float* W_src = (const float*)d_in[5];
    const float* b_src = (const float*)d_in[6];
    const float* W_tgt = (const float*)d_in[7];
    const float* b_tgt = (const float*)d_in[8];
    float* out = (float*)d_out;

    // CSR build (counting sort keyed by tgt)
    k_zero <<<(NN+255)/256, 256>>>();
    k_hist <<<(NE+255)/256, 256>>>(tgt);
    int nb = (NN + 1023) / 1024;            // 98
    k_scan1<<<nb, 1024>>>();
    k_scan2<<<1, 32>>>(nb);
    k_scan3<<<(NN+255)/256, 256>>>();
    k_fill <<<(NE+255)/256, 256>>>(src, tgt);

    // embeddings
    dim3 ge(NN/4, NS);
    k_emb<<<ge, 256>>>(data, Ws, bs);

    // 10 fused propagation steps with double buffering
    float *pA, *pB, *pE;
    cudaGetSymbolAddress((void**)&pE, g_emb);
    cudaGetSymbolAddress((void**)&pA, g_bufA);
    cudaGetSymbolAddress((void**)&pB, g_bufB);
    const float* cur = pE;
    float* nxt = pA;
    for (int d = 0; d < DEPTH; d++) {
        k_prop<<<NN/8, 256>>>(cur, nxt);
        cur = nxt;
        nxt = (cur == pA) ? pB : pA;
    }

    // fused attention epilogue
    k_final<<<NN/8, 256>>>(cur, data, W_src, b_src, W_tgt, b_tgt, out);
}

// round 2
// speedup vs baseline: 1.0025x; 1.0025x over previous
#include <cuda_runtime.h>

#define NN 100000
#define NE 1600000
#define NS 3
#define DIN 128
#define DOUT 64
#define ROW (NS*DOUT)   /* 192 floats per node state row */
#define DEPTH 10

// ---------------- device scratch (static: no allocation allowed) ----------------
__device__ float g_emb [NN*ROW];
__device__ float g_bufA[NN*ROW];
__device__ float g_bufB[NN*ROW];
__device__ int   g_cnt[NN];
__device__ int   g_rowptr[NN+1];
__device__ int   g_cursor[NN];
__device__ float g_deginv[NN];
__device__ int   g_col[NE];
__device__ int   g_scan[NN];
__device__ int   g_bsum[128];
__device__ int   g_boff[128];
__device__ int   g_done;     // zero-init at module load; reset by last scan block

// ---------------- CSR build (counting sort by tgt), 4 kernels total ----------------
__global__ void k_zero() {
    int i = blockIdx.x*blockDim.x + threadIdx.x;
    if (i < NN) g_cnt[i] = 0;
}

__global__ void k_hist(const int* __restrict__ tgt) {
    int e = blockIdx.x*blockDim.x + threadIdx.x;
    if (e < NE) atomicAdd(&g_cnt[tgt[e]], 1);
}

// fused scan: per-block inclusive scan + decoupled last-block finish
// (block offsets + rowptr/cursor/deginv for the whole graph)
__global__ void k_scan123() {
    __shared__ int sh[1024];
    __shared__ bool s_last;
    int t = threadIdx.x;
    int i = blockIdx.x*1024 + t;
    int v = (i < NN) ? g_cnt[i] : 0;
    sh[t] = v;
    __syncthreads();
    for (int off = 1; off < 1024; off <<= 1) {
        int add = (t >= off) ? sh[t-off] : 0;
        __syncthreads();
        sh[t] += add;
        __syncthreads();
    }
    if (i < NN) g_scan[i] = sh[t];
    if (t == 1023) g_bsum[blockIdx.x] = sh[1023];
    __threadfence();
    if (t == 0) {
        int done = atomicAdd(&g_done, 1);
        s_last = (done == (int)gridDim.x - 1);
    }
    __syncthreads();
    if (!s_last) return;
    __threadfence();                 // acquire all blocks' bsum/scan
    if (t == 0) {
        int run = 0;
        for (int b = 0; b < (int)gridDim.x; b++) { g_boff[b] = run; run += g_bsum[b]; }
        g_done = 0;                  // ready for next graph replay
        g_rowptr[NN] = NE;
    }
    __syncthreads();
    for (int k = t; k < NN; k += 1024) {
        int cnt  = g_cnt[k];
        int excl = g_scan[k] - cnt + g_boff[k >> 10];
        g_rowptr[k] = excl;
        g_cursor[k] = excl;
        g_deginv[k] = 1.0f / (float)max(cnt, 1);
    }
}

__global__ void k_fill(const int* __restrict__ src, const int* __restrict__ tgt) {
    int e = blockIdx.x*blockDim.x + threadIdx.x;
    if (e < NE) {
        int p = atomicAdd(&g_cursor[tgt[e]], 1);
        g_col[p] = src[e];
    }
}

// ---------------- emb = data @ Ws + bs, laid out [N][S*64] ----------------
__global__ void k_emb(const float* __restrict__ data, const float* __restrict__ Ws,
                      const float* __restrict__ bs) {
    __shared__ float sd[4*DIN];
    int s  = blockIdx.y;
    int n0 = blockIdx.x * 4;
    int tid = threadIdx.x;
    for (int i = tid; i < 4*DIN; i += 256) sd[i] = data[n0*DIN + i];
    __syncthreads();
    int ln = tid >> 6;      // 0..3  (node within block)
    int o  = tid & 63;      // output dim
    const float* W  = Ws + s*DIN*DOUT;
    const float* dr = sd + ln*DIN;
    float acc = bs[s*DOUT + o];
    #pragma unroll 8
    for (int k = 0; k < DIN; k++) acc += dr[k] * W[k*DOUT + o];
    g_emb[(n0+ln)*ROW + s*DOUT + o] = acc;
}

// ---------------- one propagation step, all 3 scales fused ----------------
// out = (1-t)*(x - mean_in(x)) + t*emb   (deg>0), else  t*emb
// Unrolled-by-4 index prefetch: 12 independent row loads in flight (MLP~12).
// emb read + y write use streaming hints so the gather target x stays L2-resident.
__global__ void __launch_bounds__(256) k_prop(const float* __restrict__ x,
                                              float* __restrict__ y) {
    int w    = (blockIdx.x*blockDim.x + threadIdx.x) >> 5;
    int lane = threadIdx.x & 31;
    if (w >= NN) return;
    int beg = g_rowptr[w], end = g_rowptr[w+1];

    float a0x=0.f,a0y=0.f,a1x=0.f,a1y=0.f,a2x=0.f,a2y=0.f;

    int j = beg;
    for (; j + 4 <= end; j += 4) {
        int c0 = __ldg(&g_col[j+0]);
        int c1 = __ldg(&g_col[j+1]);
        int c2 = __ldg(&g_col[j+2]);
        int c3 = __ldg(&g_col[j+3]);
        const float2* r0 = (const float2*)(x + (size_t)c0*ROW);
        const float2* r1 = (const float2*)(x + (size_t)c1*ROW);
        const float2* r2 = (const float2*)(x + (size_t)c2*ROW);
        const float2* r3 = (const float2*)(x + (size_t)c3*ROW);
        float2 v00 = r0[lane],    v10 = r1[lane],    v20 = r2[lane],    v30 = r3[lane];
        float2 v01 = r0[32+lane], v11 = r1[32+lane], v21 = r2[32+lane], v31 = r3[32+lane];
        float2 v02 = r0[64+lane], v12 = r1[64+lane], v22 = r2[64+lane], v32 = r3[64+lane];
        a0x += (v00.x + v10.x) + (v20.x + v30.x);
        a0y += (v00.y + v10.y) + (v20.y + v30.y);
        a1x += (v01.x + v11.x) + (v21.x + v31.x);
        a1y += (v01.y + v11.y) + (v21.y + v31.y);
        a2x += (v02.x + v12.x) + (v22.x + v32.x);
        a2y += (v02.y + v12.y) + (v22.y + v32.y);
    }
    for (; j < end; j++) {
        int c = __ldg(&g_col[j]);
        const float2* xr = (const float2*)(x + (size_t)c*ROW);
        float2 v0 = xr[lane], v1 = xr[32+lane], v2 = xr[64+lane];
        a0x += v0.x; a0y += v0.y;
        a1x += v1.x; a1y += v1.y;
        a2x += v2.x; a2y += v2.y;
    }

    const float2* em = (const float2*)(g_emb + (size_t)w*ROW);
    float2* yr = (float2*)(y + (size_t)w*ROW);
    float2 e0 = __ldcs(em + lane), e1 = __ldcs(em + 32 + lane), e2 = __ldcs(em + 64 + lane);
    const float t0 = 0.1f, t1 = 0.2f, t2 = 0.3f;

    if (end > beg) {
        float dinv = g_deginv[w];
        const float2* xo = (const float2*)(x + (size_t)w*ROW);
        float2 o0 = xo[lane], o1 = xo[32+lane], o2 = xo[64+lane];
        float2 r;
        r.x = (1.f-t0)*(o0.x - a0x*dinv) + t0*e0.x;
        r.y = (1.f-t0)*(o0.y - a0y*dinv) + t0*e0.y;  __stcs(yr + lane,      r);
        r.x = (1.f-t1)*(o1.x - a1x*dinv) + t1*e1.x;
        r.y = (1.f-t1)*(o1.y - a1y*dinv) + t1*e1.y;  __stcs(yr + 32 + lane, r);
        r.x = (1.f-t2)*(o2.x - a2x*dinv) + t2*e2.x;
        r.y = (1.f-t2)*(o2.y - a2y*dinv) + t2*e2.y;  __stcs(yr + 64 + lane, r);
    } else {
        __stcs(yr + lane,      make_float2(t0*e0.x, t0*e0.y));
        __stcs(yr + 32 + lane, make_float2(t1*e1.x, t1*e1.y));
        __stcs(yr + 64 + lane, make_float2(t2*e2.x, t2*e2.y));
    }
}

// ---------------- fused attention epilogue, warp per node ----------------
__global__ void k_final(const float* __restrict__ xin, const float* __restrict__ data,
                        const float* __restrict__ W_src, const float* __restrict__ b_src,
                        const float* __restrict__ W_tgt, const float* __restrict__ b_tgt,
                        float* __restrict__ out) {
    __shared__ float sd[8][DIN];
    __shared__ float ss[8][DOUT];
    int wid  = threadIdx.x >> 5;
    int lane = threadIdx.x & 31;
    int n = blockIdx.x*8 + wid;
    if (n >= NN) return;

    // stage the data row in shared
    float4 dv = ((const float4*)(data + (size_t)n*DIN))[lane];
    ((float4*)sd[wid])[lane] = dv;
    __syncwarp();

    // s_att[o] = b_src[o] + data[n] . W_src[:,o]  for o = lane, lane+32
    float a0 = b_src[lane], a1 = b_src[lane + 32];
    #pragma unroll 8
    for (int k = 0; k < DIN; k++) {
        float d = sd[wid][k];
        a0 += d * W_src[k*DOUT + lane];
        a1 += d * W_src[k*DOUT + lane + 32];
    }
    ss[wid][lane] = a0; ss[wid][lane + 32] = a1;
    __syncwarp();

    // scales = relu(out10)
    const float* xr = xin + (size_t)n*ROW;
    float sc[NS][2];
    #pragma unroll
    for (int s = 0; s < NS; s++) {
        sc[s][0] = fmaxf(xr[s*DOUT + lane],      0.f);
        sc[s][1] = fmaxf(xr[s*DOUT + lane + 32], 0.f);
    }

    // u[p] = W_tgt[p,:] . s_att   for p = lane, lane+32
    float u0 = 0.f, u1 = 0.f;
    #pragma unroll 8
    for (int o = 0; o < DOUT; o++) {
        float sa = ss[wid][o];
        u0 += W_tgt[lane*DOUT + o]        * sa;
        u1 += W_tgt[(lane + 32)*DOUT + o] * sa;
    }

    // c = b_tgt . s_att (warp-reduced)
    float cp = b_tgt[lane]*ss[wid][lane] + b_tgt[lane+32]*ss[wid][lane+32];
    for (int m = 16; m; m >>= 1) cp += __shfl_xor_sync(0xffffffffu, cp, m);

    // logits[s] = scales[s,:] . u + c
    float lg[NS];
    #pragma unroll
    for (int s = 0; s < NS; s++) {
        float p = sc[s][0]*u0 + sc[s][1]*u1;
        for (int m = 16; m; m >>= 1) p += __shfl_xor_sync(0xffffffffu, p, m);
        lg[s] = p + cp;
    }

    float mx = fmaxf(lg[0], fmaxf(lg[1], lg[2]));
    float e0 = expf(lg[0]-mx), e1 = expf(lg[1]-mx), e2 = expf(lg[2]-mx);
    float inv = 1.f / (e0 + e1 + e2);
    float w0 = e0*inv, w1 = e1*inv, w2 = e2*inv;

    out[(size_t)n*DOUT + lane]      = w0*sc[0][0] + w1*sc[1][0] + w2*sc[2][0];
    out[(size_t)n*DOUT + lane + 32] = w0*sc[0][1] + w1*sc[1][1] + w2*sc[2][1];
}

// ---------------- launch ----------------
extern "C" void kernel_launch(void* const* d_in, const int* in_sizes, int n_in,
                              void* d_out, int out_size) {
    const float* data  = (const float*)d_in[0];
    const int*   src   = (const int*)  d_in[1];
    const int*   tgt   = (const int*)  d_in[2];
    const float* Ws    = (const float*)d_in[3];
    const float* bs    = (const float*)d_in[4];
    const float* W_src = (const float*)d_in[5];
    const float* b_src = (const float*)d_in[6];
    const float* W_tgt = (const float*)d_in[7];
    const float* b_tgt = (const float*)d_in[8];
    float* out = (float*)d_out;

    // CSR build: 4 kernels (launch indices 0..3)
    k_zero   <<<(NN+255)/256, 256>>>();
    k_hist   <<<(NE+255)/256, 256>>>(tgt);
    k_scan123<<<(NN+1023)/1024, 1024>>>();
    k_fill   <<<(NE+255)/256, 256>>>(src, tgt);

    // embeddings (launch index 4)
    dim3 ge(NN/4, NS);
    k_emb<<<ge, 256>>>(data, Ws, bs);

    // 10 fused propagation steps with double buffering (launch 5 = first k_prop)
    float *pA, *pB, *pE;
    cudaGetSymbolAddress((void**)&pE, g_emb);
    cudaGetSymbolAddress((void**)&pA, g_bufA);
    cudaGetSymbolAddress((void**)&pB, g_bufB);
    const float* cur = pE;
    float* nxt = pA;
    for (int d = 0; d < DEPTH; d++) {
        k_prop<<<NN/8, 256>>>(cur, nxt);
        cur = nxt;
        nxt = (cur == pA) ? pB : pA;
    }

    // fused attention epilogue
    k_final<<<NN/8, 256>>>(cur, data, W_src, b_src, W_tgt, b_tgt, out);
}

// round 3
// speedup vs baseline: 1.0935x; 1.0907x over previous
#include <cuda_runtime.h>
#include <cuda_fp16.h>

#define NN 100000
#define NE 1600000
#define NS 3
#define DIN 128
#define DOUT 64
#define ROW (NS*DOUT)    /* 192 floats per node state row */
#define HROW 96          /* 96 half2 per node row */
#define DEPTH 10

// ---------------- device scratch (static: no allocation allowed) ----------------
__device__ float   g_emb [NN*ROW];
__device__ float   g_bufA[NN*ROW];
__device__ float   g_bufB[NN*ROW];
__device__ __half2 g_hA[NN*HROW];   // fp16 gather mirrors (double buffered)
__device__ __half2 g_hB[NN*HROW];
__device__ int     g_cnt[NN];
__device__ int     g_rowptr[NN+1];
__device__ int     g_cursor[NN];
__device__ float   g_deginv[NN];
__device__ int     g_col[NE];
__device__ int     g_scan[NN];
__device__ int     g_bsum[128];
__device__ int     g_boff[128];
__device__ int     g_done;

// ---------------- CSR build (counting sort by tgt), 4 kernels ----------------
__global__ void k_zero() {
    int i = blockIdx.x*blockDim.x + threadIdx.x;
    if (i < NN) g_cnt[i] = 0;
}

__global__ void k_hist(const int* __restrict__ tgt) {
    int e = blockIdx.x*blockDim.x + threadIdx.x;
    if (e < NE) atomicAdd(&g_cnt[tgt[e]], 1);
}

__global__ void k_scan123() {
    __shared__ int sh[1024];
    __shared__ bool s_last;
    int t = threadIdx.x;
    int i = blockIdx.x*1024 + t;
    int v = (i < NN) ? g_cnt[i] : 0;
    sh[t] = v;
    __syncthreads();
    for (int off = 1; off < 1024; off <<= 1) {
        int add = (t >= off) ? sh[t-off] : 0;
        __syncthreads();
        sh[t] += add;
        __syncthreads();
    }
    if (i < NN) g_scan[i] = sh[t];
    if (t == 1023) g_bsum[blockIdx.x] = sh[1023];
    __threadfence();
    if (t == 0) {
        int done = atomicAdd(&g_done, 1);
        s_last = (done == (int)gridDim.x - 1);
    }
    __syncthreads();
    if (!s_last) return;
    __threadfence();
    if (t == 0) {
        int run = 0;
        for (int b = 0; b < (int)gridDim.x; b++) { g_boff[b] = run; run += g_bsum[b]; }
        g_done = 0;
        g_rowptr[NN] = NE;
    }
    __syncthreads();
    for (int k = t; k < NN; k += 1024) {
        int cnt  = g_cnt[k];
        int excl = g_scan[k] - cnt + g_boff[k >> 10];
        g_rowptr[k] = excl;
        g_cursor[k] = excl;
        g_deginv[k] = 1.0f / (float)max(cnt, 1);
    }
}

__global__ void k_fill(const int* __restrict__ src, const int* __restrict__ tgt) {
    int e = blockIdx.x*blockDim.x + threadIdx.x;
    if (e < NE) {
        int p = atomicAdd(&g_cursor[tgt[e]], 1);
        g_col[p] = src[e];
    }
}

// ---------------- emb = data @ Ws + bs (+ fp16 mirror into g_hA) ----------------
__global__ void k_emb(const float* __restrict__ data, const float* __restrict__ Ws,
                      const float* __restrict__ bs) {
    __shared__ float sd[4*DIN];
    int s  = blockIdx.y;
    int n0 = blockIdx.x * 4;
    int tid = threadIdx.x;
    for (int i = tid; i < 4*DIN; i += 256) sd[i] = data[n0*DIN + i];
    __syncthreads();
    int ln = tid >> 6;      // node within block
    int o  = tid & 63;      // output dim
    const float* W  = Ws + s*DIN*DOUT;
    const float* dr = sd + ln*DIN;
    float acc = bs[s*DOUT + o];
    #pragma unroll 8
    for (int k = 0; k < DIN; k++) acc += dr[k] * W[k*DOUT + o];
    int node = n0 + ln;
    g_emb[(size_t)node*ROW + s*DOUT + o] = acc;
    ((__half*)g_hA)[(size_t)node*ROW + s*DOUT + o] = __float2half_rn(acc);
}

// ---------------- one propagation step, all 3 scales fused ----------------
// Gather reads come from the fp16 mirror (L2-resident, half the bytes);
// own/emb paths stay fp32 for accuracy. Writes fp32 y (streamed) + fp16 mirror (cached).
__global__ void __launch_bounds__(256) k_prop(const float* __restrict__ x,
                                              const __half2* __restrict__ xh,
                                              float* __restrict__ y,
                                              __half2* __restrict__ yh) {
    int w    = (blockIdx.x*blockDim.x + threadIdx.x) >> 5;
    int lane = threadIdx.x & 31;
    if (w >= NN) return;
    int beg = g_rowptr[w], end = g_rowptr[w+1];

    float a0x=0.f,a0y=0.f,a1x=0.f,a1y=0.f,a2x=0.f,a2y=0.f;

    int j = beg;
    for (; j + 4 <= end; j += 4) {
        int c0 = __ldg(&g_col[j+0]);
        int c1 = __ldg(&g_col[j+1]);
        int c2 = __ldg(&g_col[j+2]);
        int c3 = __ldg(&g_col[j+3]);
        const __half2* r0 = xh + (size_t)c0*HROW;
        const __half2* r1 = xh + (size_t)c1*HROW;
        const __half2* r2 = xh + (size_t)c2*HROW;
        const __half2* r3 = xh + (size_t)c3*HROW;
        float2 v00 = __half22float2(r0[lane]);
        float2 v10 = __half22float2(r1[lane]);
        float2 v20 = __half22float2(r2[lane]);
        float2 v30 = __half22float2(r3[lane]);
        float2 v01 = __half22float2(r0[32+lane]);
        float2 v11 = __half22float2(r1[32+lane]);
        float2 v21 = __half22float2(r2[32+lane]);
        float2 v31 = __half22float2(r3[32+lane]);
        float2 v02 = __half22float2(r0[64+lane]);
        float2 v12 = __half22float2(r1[64+lane]);
        float2 v22 = __half22float2(r2[64+lane]);
        float2 v32 = __half22float2(r3[64+lane]);
        a0x += (v00.x + v10.x) + (v20.x + v30.x);
        a0y += (v00.y + v10.y) + (v20.y + v30.y);
        a1x += (v01.x + v11.x) + (v21.x + v31.x);
        a1y += (v01.y + v11.y) + (v21.y + v31.y);
        a2x += (v02.x + v12.x) + (v22.x + v32.x);
        a2y += (v02.y + v12.y) + (v22.y + v32.y);
    }
    for (; j < end; j++) {
        int c = __ldg(&g_col[j]);
        const __half2* r = xh + (size_t)c*HROW;
        float2 v0 = __half22float2(r[lane]);
        float2 v1 = __half22float2(r[32+lane]);
        float2 v2 = __half22float2(r[64+lane]);
        a0x += v0.x; a0y += v0.y;
        a1x += v1.x; a1y += v1.y;
        a2x += v2.x; a2y += v2.y;
    }

    const float2* em = (const float2*)(g_emb + (size_t)w*ROW);
    float2* yr = (float2*)(y + (size_t)w*ROW);
    __half2* hr = yh + (size_t)w*HROW;
    float2 e0 = __ldcs(em + lane), e1 = __ldcs(em + 32 + lane), e2 = __ldcs(em + 64 + lane);
    const float t0 = 0.1f, t1 = 0.2f, t2 = 0.3f;

    float2 r;
    if (end > beg) {
        float dinv = g_deginv[w];
        const float2* xo = (const float2*)(x + (size_t)w*ROW);
        float2 o0 = __ldcs(xo + lane), o1 = __ldcs(xo + 32 + lane), o2 = __ldcs(xo + 64 + lane);
        r.x = (1.f-t0)*(o0.x - a0x*dinv) + t0*e0.x;
        r.y = (1.f-t0)*(o0.y - a0y*dinv) + t0*e0.y;
        __stcs(yr + lane, r);            hr[lane]      = __float22half2_rn(r);
        r.x = (1.f-t1)*(o1.x - a1x*dinv) + t1*e1.x;
        r.y = (1.f-t1)*(o1.y - a1y*dinv) + t1*e1.y;
        __stcs(yr + 32 + lane, r);       hr[32 + lane] = __float22half2_rn(r);
        r.x = (1.f-t2)*(o2.x - a2x*dinv) + t2*e2.x;
        r.y = (1.f-t2)*(o2.y - a2y*dinv) + t2*e2.y;
        __stcs(yr + 64 + lane, r);       hr[64 + lane] = __float22half2_rn(r);
    } else {
        r = make_float2(t0*e0.x, t0*e0.y);
        __stcs(yr + lane, r);            hr[lane]      = __float22half2_rn(r);
        r = make_float2(t1*e1.x, t1*e1.y);
        __stcs(yr + 32 + lane, r);       hr[32 + lane] = __float22half2_rn(r);
        r = make_float2(t2*e2.x, t2*e2.y);
        __stcs(yr + 64 + lane, r);       hr[64 + lane] = __float22half2_rn(r);
    }
}

// ---------------- fused attention epilogue, warp per node ----------------
__global__ void k_final(const float* __restrict__ xin, const float* __restrict__ data,
                        const float* __restrict__ W_src, const float* __restrict__ b_src,
                        const float* __restrict__ W_tgt, const float* __restrict__ b_tgt,
                        float* __restrict__ out) {
    __shared__ float sd[8][DIN];
    __shared__ float ss[8][DOUT];
    int wid  = threadIdx.x >> 5;
    int lane = threadIdx.x & 31;
    int n = blockIdx.x*8 + wid;
    if (n >= NN) return;

    float4 dv = ((const float4*)(data + (size_t)n*DIN))[lane];
    ((float4*)sd[wid])[lane] = dv;
    __syncwarp();

    float a0 = b_src[lane], a1 = b_src[lane + 32];
    #pragma unroll 8
    for (int k = 0; k < DIN; k++) {
        float d = sd[wid][k];
        a0 += d * W_src[k*DOUT + lane];
        a1 += d * W_src[k*DOUT + lane + 32];
    }
    ss[wid][lane] = a0; ss[wid][lane + 32] = a1;
    __syncwarp();

    const float* xr = xin + (size_t)n*ROW;
    float sc[NS][2];
    #pragma unroll
    for (int s = 0; s < NS; s++) {
        sc[s][0] = fmaxf(xr[s*DOUT + lane],      0.f);
        sc[s][1] = fmaxf(xr[s*DOUT + lane + 32], 0.f);
    }

    float u0 = 0.f, u1 = 0.f;
    #pragma unroll 8
    for (int o = 0; o < DOUT; o++) {
        float sa = ss[wid][o];
        u0 += W_tgt[lane*DOUT + o]        * sa;
        u1 += W_tgt[(lane + 32)*DOUT + o] * sa;
    }

    float cp = b_tgt[lane]*ss[wid][lane] + b_tgt[lane+32]*ss[wid][lane+32];
    for (int m = 16; m; m >>= 1) cp += __shfl_xor_sync(0xffffffffu, cp, m);

    float lg[NS];
    #pragma unroll
    for (int s = 0; s < NS; s++) {
        float p = sc[s][0]*u0 + sc[s][1]*u1;
        for (int m = 16; m; m >>= 1) p += __shfl_xor_sync(0xffffffffu, p, m);
        lg[s] = p + cp;
    }

    float mx = fmaxf(lg[0], fmaxf(lg[1], lg[2]));
    float e0 = expf(lg[0]-mx), e1 = expf(lg[1]-mx), e2 = expf(lg[2]-mx);
    float inv = 1.f / (e0 + e1 + e2);
    float w0 = e0*inv, w1 = e1*inv, w2 = e2*inv;

    out[(size_t)n*DOUT + lane]      = w0*sc[0][0] + w1*sc[1][0] + w2*sc[2][0];
    out[(size_t)n*DOUT + lane + 32] = w0*sc[0][1] + w1*sc[1][1] + w2*sc[2][1];
}

// ---------------- launch ----------------
extern "C" void kernel_launch(void* const* d_in, const int* in_sizes, int n_in,
                              void* d_out, int out_size) {
    const float* data  = (const float*)d_in[0];
    const int*   src   = (const int*)  d_in[1];
    const int*   tgt   = (const int*)  d_in[2];
    const float* Ws    = (const float*)d_in[3];
    const float* bs    = (const float*)d_in[4];
    const float* W_src = (const float*)d_in[5];
    const float* b_src = (const float*)d_in[6];
    const float* W_tgt = (const float*)d_in[7];
    const float* b_tgt = (const float*)d_in[8];
    float* out = (float*)d_out;

    // CSR build: launches 0..3
    k_zero   <<<(NN+255)/256, 256>>>();
    k_hist   <<<(NE+255)/256, 256>>>(tgt);
    k_scan123<<<(NN+1023)/1024, 1024>>>();
    k_fill   <<<(NE+255)/256, 256>>>(src, tgt);

    // embeddings + fp16 mirror into g_hA (launch 4)
    dim3 ge(NN/4, NS);
    k_emb<<<ge, 256>>>(data, Ws, bs);

    float *pA, *pB, *pE;
    __half2 *hA, *hB;
    cudaGetSymbolAddress((void**)&pE, g_emb);
    cudaGetSymbolAddress((void**)&pA, g_bufA);
    cudaGetSymbolAddress((void**)&pB, g_bufB);
    cudaGetSymbolAddress((void**)&hA, g_hA);
    cudaGetSymbolAddress((void**)&hB, g_hB);

    // 10 fused propagation steps; launch 5 = first k_prop (ncu window)
    const float*   cur  = pE;
    const __half2* curh = hA;
    float*   nxt  = pA;
    __half2* nxth = hB;
    for (int d = 0; d < DEPTH; d++) {
        k_prop<<<NN/8, 256>>>(cur, curh, nxt, nxth);
        cur  = nxt;  curh = nxth;
        nxt  = (cur  == pA) ? pB : pA;
        nxth = (curh == hA) ? hB : hA;
    }

    // fused attention epilogue
    k_final<<<NN/8, 256>>>(cur, data, W_src, b_src, W_tgt, b_tgt, out);
}